// round 1
// baseline (speedup 1.0000x reference)
#include <cuda_runtime.h>

#define TOKENS 16384
#define DMODEL 768
#define DFFN   3072
#define NHEAD  8
#define HDIM   96
#define NBLK   64
#define BLKS   64
#define NKBS   5
#define SEQ    4096
#define BATCH  4

// ---------------- scratch (static device globals; no allocation) ----------------
__device__ float g_h  [TOKENS * DMODEL];
__device__ float g_q  [TOKENS * DMODEL];
__device__ float g_k  [TOKENS * DMODEL];
__device__ float g_v  [TOKENS * DMODEL];
__device__ float g_ctx[TOKENS * DMODEL];
__device__ float g_x  [TOKENS * DMODEL];
__device__ float g_ffn[TOKENS * DFFN];

// ---------------- LayerNorm: one block per row ----------------
__global__ void __launch_bounds__(256) ln_kernel(const float* __restrict__ x,
                                                 const float* __restrict__ gam,
                                                 const float* __restrict__ bet,
                                                 float* __restrict__ out) {
    int row = blockIdx.x;
    const float* xr = x + (size_t)row * DMODEL;
    int t = threadIdx.x;
    float v0 = xr[t], v1 = xr[t + 256], v2 = xr[t + 512];
    float s  = v0 + v1 + v2;
    float sq = v0 * v0 + v1 * v1 + v2 * v2;
#pragma unroll
    for (int o = 16; o; o >>= 1) {
        s  += __shfl_xor_sync(0xffffffffu, s, o);
        sq += __shfl_xor_sync(0xffffffffu, sq, o);
    }
    __shared__ float rs_[8], rq_[8];
    if ((t & 31) == 0) { rs_[t >> 5] = s; rq_[t >> 5] = sq; }
    __syncthreads();
    s = 0.f; sq = 0.f;
#pragma unroll
    for (int w = 0; w < 8; w++) { s += rs_[w]; sq += rq_[w]; }
    float m   = s * (1.f / DMODEL);
    float var = sq * (1.f / DMODEL) - m * m;
    float inv = rsqrtf(var + 1e-5f);
    float* orow = out + (size_t)row * DMODEL;
    orow[t]       = (v0 - m) * inv * gam[t]       + bet[t];
    orow[t + 256] = (v1 - m) * inv * gam[t + 256] + bet[t + 256];
    orow[t + 512] = (v2 - m) * inv * gam[t + 512] + bet[t + 512];
}

// ---------------- SGEMM: C = A[MxK] * W[KxN] + bias (+resid) (relu?) ----------------
// BM=BN=128, BK=8, 256 threads, 8x8 microtile per thread.
__global__ void __launch_bounds__(256) sgemm_kernel(const float* __restrict__ A,
                                                    const float* __restrict__ W,
                                                    const float* __restrict__ bias,
                                                    const float* __restrict__ resid,
                                                    float* __restrict__ C,
                                                    int M, int N, int K, int relu) {
    constexpr int BM = 128, BN = 128, BK = 8;
    __shared__ float As[BK][BM];
    __shared__ float Bs[BK][BN];
    int tid  = threadIdx.x;
    int brow = blockIdx.y * BM;
    int bcol = blockIdx.x * BN;
    int tr = tid >> 4;        // 0..15
    int tc = tid & 15;        // 0..15

    float acc[8][8];
#pragma unroll
    for (int i = 0; i < 8; i++)
#pragma unroll
        for (int j = 0; j < 8; j++) acc[i][j] = 0.f;

    int arow  = tid >> 1;           // 0..127
    int akoff = (tid & 1) * 4;      // 0 or 4
    int bk    = tid >> 5;           // 0..7
    int bn    = (tid & 31) * 4;     // 0..124

    const float* Aptr = A + (size_t)(brow + arow) * K + akoff;
    const float* Wptr = W + (size_t)bk * N + bcol + bn;

    for (int k0 = 0; k0 < K; k0 += BK) {
        float4 av = *(const float4*)(Aptr + k0);
        float4 bv = *(const float4*)(Wptr + (size_t)k0 * N);
        As[akoff + 0][arow] = av.x;
        As[akoff + 1][arow] = av.y;
        As[akoff + 2][arow] = av.z;
        As[akoff + 3][arow] = av.w;
        *(float4*)&Bs[bk][bn] = bv;
        __syncthreads();
#pragma unroll
        for (int kk = 0; kk < BK; kk++) {
            float ar[8], br[8];
#pragma unroll
            for (int i = 0; i < 8; i++) ar[i] = As[kk][tr * 8 + i];
#pragma unroll
            for (int j = 0; j < 8; j++) br[j] = Bs[kk][tc * 8 + j];
#pragma unroll
            for (int i = 0; i < 8; i++)
#pragma unroll
                for (int j = 0; j < 8; j++) acc[i][j] += ar[i] * br[j];
        }
        __syncthreads();
    }

    // epilogue
#pragma unroll
    for (int i = 0; i < 8; i++) {
        int r = brow + tr * 8 + i;
        size_t rowoff = (size_t)r * N + bcol + tc * 8;
        float* cp = C + rowoff;
        const float* rp = resid ? resid + rowoff : nullptr;
#pragma unroll
        for (int j = 0; j < 8; j++) {
            float v = acc[i][j] + bias[bcol + tc * 8 + j];
            if (relu) v = fmaxf(v, 0.f);
            if (rp) v += rp[j];
            cp[j] = v;
        }
    }
}

// ---------------- BigBird block attention ----------------
// grid (NBLK, NHEAD, BATCH), 256 threads. All-fp32.
#define QS  97      // q_s row stride
#define KTS 68      // transposed-K row stride (by d), float4-aligned
#define VS  97      // v row stride
#define SCS 324     // score row stride (320 + 4)
#define OFF_Q   0
#define OFF_KV  (64 * QS)               // 6208
#define OFF_SC  (OFF_KV + 96 * KTS)     // 6208 + 6528 = 12736
#define OFF_INV (OFF_SC + 64 * SCS)     // 12736 + 20736 = 33472
#define ATTN_SMEM_BYTES ((OFF_INV + 64) * 4)   // 134144 B

__global__ void __launch_bounds__(256) attn_kernel(const float* __restrict__ Q,
                                                   const float* __restrict__ K,
                                                   const float* __restrict__ V,
                                                   const int* __restrict__ kb_idx,
                                                   float* __restrict__ ctx) {
    extern __shared__ float sm[];
    float* q_s  = sm + OFF_Q;
    float* kv   = sm + OFF_KV;
    float* sc   = sm + OFF_SC;
    float* rinv = sm + OFF_INV;

    int i  = blockIdx.x;
    int hh = blockIdx.y;
    int b  = blockIdx.z;
    int tid = threadIdx.x;
    int base = b * SEQ + i * BLKS;
    const float scale = rsqrtf((float)HDIM);

    // load + pre-scale Q block [64 x 96]
    for (int idx = tid; idx < BLKS * HDIM; idx += 256) {
        int qq = idx / HDIM, d = idx % HDIM;
        q_s[qq * QS + d] = Q[(size_t)(base + qq) * DMODEL + hh * HDIM + d] * scale;
    }

    int  kbv[NKBS];
    bool val[NKBS], dia[NKBS];
#pragma unroll
    for (int s = 0; s < NKBS; s++) {
        kbv[s] = kb_idx[i * NKBS + s];
        val[s] = (s == 0) || (kbv[s] != 0);   // slot validity (block 0 only ever in slot 0)
        dia[s] = (kbv[s] == i);               // diagonal slot -> within-block causal mask
    }

    int sq0 = (tid >> 4) * 4;   // score tile: 4q x 4p
    int sp0 = (tid & 15) * 4;
    __syncthreads();

    // ---- phase 1: scores for all 5 slots ----
    for (int s = 0; s < NKBS; s++) {
        if (val[s]) {
            __syncthreads();   // prior users of kv done
            int kbase = b * SEQ + kbv[s] * BLKS;
            for (int idx = tid; idx < BLKS * HDIM; idx += 256) {
                int p = idx / HDIM, d = idx % HDIM;
                kv[d * KTS + p] = K[(size_t)(kbase + p) * DMODEL + hh * HDIM + d];
            }
            __syncthreads();
            float acc00=0,acc01=0,acc02=0,acc03=0;
            float acc10=0,acc11=0,acc12=0,acc13=0;
            float acc20=0,acc21=0,acc22=0,acc23=0;
            float acc30=0,acc31=0,acc32=0,acc33=0;
#pragma unroll 4
            for (int d = 0; d < HDIM; d++) {
                float4 bv = *(const float4*)&kv[d * KTS + sp0];
                float a0 = q_s[(sq0 + 0) * QS + d];
                float a1 = q_s[(sq0 + 1) * QS + d];
                float a2 = q_s[(sq0 + 2) * QS + d];
                float a3 = q_s[(sq0 + 3) * QS + d];
                acc00 += a0*bv.x; acc01 += a0*bv.y; acc02 += a0*bv.z; acc03 += a0*bv.w;
                acc10 += a1*bv.x; acc11 += a1*bv.y; acc12 += a1*bv.z; acc13 += a1*bv.w;
                acc20 += a2*bv.x; acc21 += a2*bv.y; acc22 += a2*bv.z; acc23 += a2*bv.w;
                acc30 += a3*bv.x; acc31 += a3*bv.y; acc32 += a3*bv.z; acc33 += a3*bv.w;
            }
            bool dg = dia[s];
            float r[4][4] = {{acc00,acc01,acc02,acc03},{acc10,acc11,acc12,acc13},
                             {acc20,acc21,acc22,acc23},{acc30,acc31,acc32,acc33}};
#pragma unroll
            for (int a = 0; a < 4; a++)
#pragma unroll
                for (int c = 0; c < 4; c++) {
                    int qq = sq0 + a, p = sp0 + c;
                    float v = r[a][c];
                    if (dg && p > qq) v = -1e9f;
                    sc[qq * SCS + s * BLKS + p] = v;
                }
        } else {
            for (int idx = tid; idx < BLKS * BLKS; idx += 256) {
                int qq = idx >> 6, p = idx & 63;
                sc[qq * SCS + s * BLKS + p] = -1e9f;
            }
        }
    }
    __syncthreads();

    // ---- softmax over 320 per row (4 threads/row) ----
    {
        int qq = tid >> 2, l4 = tid & 3;
        float* row = sc + qq * SCS;
        float m = -1e30f;
        for (int idx = l4; idx < NKBS * BLKS; idx += 4) m = fmaxf(m, row[idx]);
        m = fmaxf(m, __shfl_xor_sync(0xffffffffu, m, 1));
        m = fmaxf(m, __shfl_xor_sync(0xffffffffu, m, 2));
        float ss = 0.f;
        for (int idx = l4; idx < NKBS * BLKS; idx += 4) {
            float e = __expf(row[idx] - m);
            row[idx] = e;
            ss += e;
        }
        ss += __shfl_xor_sync(0xffffffffu, ss, 1);
        ss += __shfl_xor_sync(0xffffffffu, ss, 2);
        if (l4 == 0) rinv[qq] = 1.f / ss;
    }
    __syncthreads();

    // ---- phase 2: ctx = probs @ V ----
    int cq0 = (tid >> 4) * 4;   // ctx tile: 4q x 6d
    int cd0 = (tid & 15) * 6;
    float cacc[4][6];
#pragma unroll
    for (int a = 0; a < 4; a++)
#pragma unroll
        for (int k = 0; k < 6; k++) cacc[a][k] = 0.f;

    for (int s = 0; s < NKBS; s++) {
        if (!val[s]) continue;   // uniform across block
        __syncthreads();
        int kbase = b * SEQ + kbv[s] * BLKS;
        for (int idx = tid; idx < BLKS * HDIM; idx += 256) {
            int p = idx / HDIM, d = idx % HDIM;
            kv[p * VS + d] = V[(size_t)(kbase + p) * DMODEL + hh * HDIM + d];
        }
        __syncthreads();
#pragma unroll 2
        for (int p = 0; p < BLKS; p++) {
            float pr0 = sc[(cq0 + 0) * SCS + s * BLKS + p];
            float pr1 = sc[(cq0 + 1) * SCS + s * BLKS + p];
            float pr2 = sc[(cq0 + 2) * SCS + s * BLKS + p];
            float pr3 = sc[(cq0 + 3) * SCS + s * BLKS + p];
            const float* vp = &kv[p * VS + cd0];
#pragma unroll
            for (int k = 0; k < 6; k++) {
                float vv = vp[k];
                cacc[0][k] += pr0 * vv;
                cacc[1][k] += pr1 * vv;
                cacc[2][k] += pr2 * vv;
                cacc[3][k] += pr3 * vv;
            }
        }
    }

    float r0 = rinv[cq0 + 0], r1 = rinv[cq0 + 1], r2 = rinv[cq0 + 2], r3 = rinv[cq0 + 3];
#pragma unroll
    for (int k = 0; k < 6; k++) {
        ctx[(size_t)(base + cq0 + 0) * DMODEL + hh * HDIM + cd0 + k] = cacc[0][k] * r0;
        ctx[(size_t)(base + cq0 + 1) * DMODEL + hh * HDIM + cd0 + k] = cacc[1][k] * r1;
        ctx[(size_t)(base + cq0 + 2) * DMODEL + hh * HDIM + cd0 + k] = cacc[2][k] * r2;
        ctx[(size_t)(base + cq0 + 3) * DMODEL + hh * HDIM + cd0 + k] = cacc[3][k] * r3;
    }
}

// ---------------- host launcher ----------------
extern "C" void kernel_launch(void* const* d_in, const int* in_sizes, int n_in,
                              void* d_out, int out_size) {
    const float* x    = (const float*)d_in[0];
    const float* Wq   = (const float*)d_in[1];
    const float* bq   = (const float*)d_in[2];
    const float* Wk   = (const float*)d_in[3];
    const float* bk   = (const float*)d_in[4];
    const float* Wv   = (const float*)d_in[5];
    const float* bv   = (const float*)d_in[6];
    const float* Wo   = (const float*)d_in[7];
    const float* bo   = (const float*)d_in[8];
    const float* ln_g = (const float*)d_in[9];
    const float* ln_b = (const float*)d_in[10];
    const float* W1   = (const float*)d_in[11];
    const float* b1   = (const float*)d_in[12];
    const float* W2   = (const float*)d_in[13];
    const float* b2   = (const float*)d_in[14];
    const int*   kb   = (const int*)d_in[15];
    float* out = (float*)d_out;

    float *ph, *pq, *pk, *pv, *pctx, *px, *pffn;
    cudaGetSymbolAddress((void**)&ph,   g_h);
    cudaGetSymbolAddress((void**)&pq,   g_q);
    cudaGetSymbolAddress((void**)&pk,   g_k);
    cudaGetSymbolAddress((void**)&pv,   g_v);
    cudaGetSymbolAddress((void**)&pctx, g_ctx);
    cudaGetSymbolAddress((void**)&px,   g_x);
    cudaGetSymbolAddress((void**)&pffn, g_ffn);

    cudaFuncSetAttribute(attn_kernel, cudaFuncAttributeMaxDynamicSharedMemorySize,
                         ATTN_SMEM_BYTES);

    dim3 gProj(DMODEL / 128, TOKENS / 128);   // (6,128)
    dim3 gFfn1(DFFN / 128, TOKENS / 128);     // (24,128)

    // h = LN(x)
    ln_kernel<<<TOKENS, 256>>>(x, ln_g, ln_b, ph);
    // qkv
    sgemm_kernel<<<gProj, 256>>>(ph, Wq, bq, nullptr, pq, TOKENS, DMODEL, DMODEL, 0);
    sgemm_kernel<<<gProj, 256>>>(ph, Wk, bk, nullptr, pk, TOKENS, DMODEL, DMODEL, 0);
    sgemm_kernel<<<gProj, 256>>>(ph, Wv, bv, nullptr, pv, TOKENS, DMODEL, DMODEL, 0);
    // attention
    attn_kernel<<<dim3(NBLK, NHEAD, BATCH), 256, ATTN_SMEM_BYTES>>>(pq, pk, pv, kb, pctx);
    // x = x + ctx @ Wo + bo
    sgemm_kernel<<<gProj, 256>>>(pctx, Wo, bo, x, px, TOKENS, DMODEL, DMODEL, 0);
    // h2 = LN(x)
    ln_kernel<<<TOKENS, 256>>>(px, ln_g, ln_b, ph);
    // ffn
    sgemm_kernel<<<gFfn1, 256>>>(ph, W1, b1, nullptr, pffn, TOKENS, DFFN, DMODEL, 1);
    sgemm_kernel<<<gProj, 256>>>(pffn, W2, b2, px, out, TOKENS, DMODEL, DFFN, 0);
}

// round 3
// speedup vs baseline: 1.7155x; 1.7155x over previous
#include <cuda_runtime.h>
#include <cuda_bf16.h>
#include <cstdint>

#define TOKENS 16384
#define DMODEL 768
#define DFFN   3072
#define NHEAD  8
#define HDIM   96
#define NBLK   64
#define BLKS   64
#define NKBS   5
#define SEQ    4096
#define BATCH  4

// ---------------- scratch (static device globals; no allocation) ----------------
__device__ uint32_t g_hP  [TOKENS * DMODEL];   // packed bf16x2 (hi|lo<<16)
__device__ uint32_t g_ctxP[TOKENS * DMODEL];
__device__ uint32_t g_ffnP[TOKENS * DFFN];
__device__ float    g_q  [TOKENS * DMODEL];
__device__ float    g_k  [TOKENS * DMODEL];
__device__ float    g_v  [TOKENS * DMODEL];
__device__ float    g_x  [TOKENS * DMODEL];
__device__ uint32_t g_wqT[DMODEL * DMODEL];    // transposed + packed weights [N][K]
__device__ uint32_t g_wkT[DMODEL * DMODEL];
__device__ uint32_t g_wvT[DMODEL * DMODEL];
__device__ uint32_t g_woT[DMODEL * DMODEL];
__device__ uint32_t g_w1T[DFFN * DMODEL];
__device__ uint32_t g_w2T[DMODEL * DFFN];

// ---------------- helpers ----------------
__device__ __forceinline__ uint32_t smem_u32(const void* p) {
    uint32_t a;
    asm("{ .reg .u64 t; cvta.to.shared.u64 t, %1; cvt.u32.u64 %0, t; }" : "=r"(a) : "l"(p));
    return a;
}
__device__ __forceinline__ uint32_t pack_bf(float f) {
    __nv_bfloat16 h = __float2bfloat16(f);
    float r = f - __bfloat162float(h);
    __nv_bfloat16 l = __float2bfloat16(r);
    return (uint32_t)__bfloat16_as_ushort(h) | ((uint32_t)__bfloat16_as_ushort(l) << 16);
}
__device__ __forceinline__ uint32_t prmt(uint32_t a, uint32_t b, uint32_t s) {
    uint32_t d;
    asm("prmt.b32 %0, %1, %2, %3;" : "=r"(d) : "r"(a), "r"(b), "r"(s));
    return d;
}
__device__ __forceinline__ void lds64(uint32_t addr, uint32_t& p0, uint32_t& p1) {
    asm volatile("ld.shared.v2.u32 {%0, %1}, [%2];" : "=r"(p0), "=r"(p1) : "r"(addr));
}
__device__ __forceinline__ void mma16816(float* c, uint32_t a0, uint32_t a1, uint32_t a2,
                                         uint32_t a3, uint32_t b0, uint32_t b1) {
    asm volatile(
        "mma.sync.aligned.m16n8k16.row.col.f32.bf16.bf16.f32 "
        "{%0,%1,%2,%3}, {%4,%5,%6,%7}, {%8,%9}, {%0,%1,%2,%3};"
        : "+f"(c[0]), "+f"(c[1]), "+f"(c[2]), "+f"(c[3])
        : "r"(a0), "r"(a1), "r"(a2), "r"(a3), "r"(b0), "r"(b1));
}
#define CP16(dst, src) \
    asm volatile("cp.async.cg.shared.global [%0], [%1], 16;" :: "r"(dst), "l"(src))
#define CP_COMMIT() asm volatile("cp.async.commit_group;" ::: "memory")
#define CP_WAIT2()  asm volatile("cp.async.wait_group 2;" ::: "memory")

// ---------------- bf16x3 tensor-core GEMM ----------------
// C[M,N] = A[M,K] @ W[K,N]; A,BT pre-packed u32 (bf16 hi|lo). BM=BN=128, BK=32.
// 256 threads, 8 warps of 64x32, 3-stage cp.async pipeline.
#define ROWU   40                        // padded row stride in u32 (160B, 16B-aligned)
#define STG_OP (128 * ROWU * 4)          // 20480 B per operand per stage
#define STG_SZ (2 * STG_OP)              // 40960 B per stage
#define GSMEM  (3 * STG_SZ)              // 122880 B

__global__ void __launch_bounds__(256) gemm_bf3_kernel(const uint32_t* __restrict__ A,
                                                       const uint32_t* __restrict__ BT,
                                                       const float* __restrict__ bias,
                                                       const float* __restrict__ resid,
                                                       float* __restrict__ C,
                                                       uint32_t* __restrict__ Cp,
                                                       int K, int N, int relu) {
    extern __shared__ char smem[];
    uint32_t sbase = smem_u32(smem);
    int tid  = threadIdx.x;
    int brow = blockIdx.y * 128;
    int bcol = blockIdx.x * 128;

    int w  = tid >> 5, l = tid & 31;
    int g  = l >> 2, tg = l & 3;
    int wm = (w >> 2) * 64;          // 0 or 64
    int wn = (w & 3) * 32;           // 0,32,64,96

    // fetch assignment: each thread copies 4x16B of A and 4x16B of B per chunk
    int fr = tid >> 1;               // row 0..127
    int fq = (tid & 1) * 4;          // seg 0..3 or 4..7
    const uint32_t* gA = A  + (size_t)(brow + fr) * K;
    const uint32_t* gB = BT + (size_t)(bcol + fr) * K;
    uint32_t sA_off = (uint32_t)(fr * ROWU) * 4;
    int nch = K >> 5;

#define FETCH(stage, c_) do {                                                   \
    uint32_t sa_ = sbase + (stage) * STG_SZ + sA_off;                           \
    uint32_t sb_ = sa_ + STG_OP;                                                \
    const uint32_t* ga_ = gA + (c_) * 32;                                       \
    const uint32_t* gb_ = gB + (c_) * 32;                                       \
    CP16(sa_ + (fq + 0) * 16, ga_ + (fq + 0) * 4);                              \
    CP16(sa_ + (fq + 1) * 16, ga_ + (fq + 1) * 4);                              \
    CP16(sa_ + (fq + 2) * 16, ga_ + (fq + 2) * 4);                              \
    CP16(sa_ + (fq + 3) * 16, ga_ + (fq + 3) * 4);                              \
    CP16(sb_ + (fq + 0) * 16, gb_ + (fq + 0) * 4);                              \
    CP16(sb_ + (fq + 1) * 16, gb_ + (fq + 1) * 4);                              \
    CP16(sb_ + (fq + 2) * 16, gb_ + (fq + 2) * 4);                              \
    CP16(sb_ + (fq + 3) * 16, gb_ + (fq + 3) * 4);                              \
} while (0)

    float acc[4][4][4];
#pragma unroll
    for (int mt = 0; mt < 4; mt++)
#pragma unroll
        for (int nt = 0; nt < 4; nt++)
#pragma unroll
            for (int j = 0; j < 4; j++) acc[mt][nt][j] = 0.f;

    FETCH(0, 0); CP_COMMIT();
    FETCH(1, 1); CP_COMMIT();

    int stage = 0;
    for (int c = 0; c < nch; c++) {
        int fs = c + 2;
        if (fs < nch) { int st = fs - (fs / 3) * 3; FETCH(st, fs); }
        CP_COMMIT();
        CP_WAIT2();
        __syncthreads();

        uint32_t sa = sbase + stage * STG_SZ;
        uint32_t sb = sa + STG_OP;
#pragma unroll
        for (int h = 0; h < 2; h++) {
            uint32_t ah[4][4], al[4][4];
#pragma unroll
            for (int mt = 0; mt < 4; mt++) {
                uint32_t base = sa + (uint32_t)((wm + mt * 16 + g) * ROWU + h * 16 + tg * 2) * 4;
                uint32_t p0, p1;
                lds64(base,                 p0, p1);
                ah[mt][0] = prmt(p0, p1, 0x5410); al[mt][0] = prmt(p0, p1, 0x7632);
                lds64(base + 8 * ROWU * 4,  p0, p1);
                ah[mt][1] = prmt(p0, p1, 0x5410); al[mt][1] = prmt(p0, p1, 0x7632);
                lds64(base + 32,            p0, p1);
                ah[mt][2] = prmt(p0, p1, 0x5410); al[mt][2] = prmt(p0, p1, 0x7632);
                lds64(base + 8 * ROWU * 4 + 32, p0, p1);
                ah[mt][3] = prmt(p0, p1, 0x5410); al[mt][3] = prmt(p0, p1, 0x7632);
            }
#pragma unroll
            for (int nt = 0; nt < 4; nt++) {
                uint32_t bbase = sb + (uint32_t)((wn + nt * 8 + g) * ROWU + h * 16 + tg * 2) * 4;
                uint32_t p0, p1;
                lds64(bbase,      p0, p1);
                uint32_t bh0 = prmt(p0, p1, 0x5410), bl0 = prmt(p0, p1, 0x7632);
                lds64(bbase + 32, p0, p1);
                uint32_t bh1 = prmt(p0, p1, 0x5410), bl1 = prmt(p0, p1, 0x7632);
#pragma unroll
                for (int mt = 0; mt < 4; mt++) {
                    mma16816(acc[mt][nt], ah[mt][0], ah[mt][1], ah[mt][2], ah[mt][3], bh0, bh1);
                    mma16816(acc[mt][nt], ah[mt][0], ah[mt][1], ah[mt][2], ah[mt][3], bl0, bl1);
                    mma16816(acc[mt][nt], al[mt][0], al[mt][1], al[mt][2], al[mt][3], bh0, bh1);
                }
            }
        }
        __syncthreads();
        stage++; if (stage == 3) stage = 0;
    }

    // epilogue
#pragma unroll
    for (int mt = 0; mt < 4; mt++) {
#pragma unroll
        for (int half = 0; half < 2; half++) {
            int r = brow + wm + mt * 16 + g + half * 8;
#pragma unroll
            for (int nt = 0; nt < 4; nt++) {
                int col = bcol + wn + nt * 8 + tg * 2;
                float v0 = acc[mt][nt][half * 2 + 0] + __ldg(&bias[col + 0]);
                float v1 = acc[mt][nt][half * 2 + 1] + __ldg(&bias[col + 1]);
                if (relu) { v0 = fmaxf(v0, 0.f); v1 = fmaxf(v1, 0.f); }
                size_t off = (size_t)r * N + col;
                if (resid) {
                    float2 rv = *(const float2*)(resid + off);
                    v0 += rv.x; v1 += rv.y;
                }
                if (Cp) {
                    uint2 pv; pv.x = pack_bf(v0); pv.y = pack_bf(v1);
                    *(uint2*)(Cp + off) = pv;
                } else {
                    float2 fv; fv.x = v0; fv.y = v1;
                    *(float2*)(C + off) = fv;
                }
            }
        }
    }
}

// ---------------- weight transpose + pack: out[C][R] = pack(in[R][C]) ----------------
__global__ void __launch_bounds__(256) transpose_pack_kernel(const float* __restrict__ in,
                                                             uint32_t* __restrict__ out,
                                                             int R, int Ccols) {
    __shared__ float t[32][33];
    int bx = blockIdx.x * 32, by = blockIdx.y * 32;
    int x = threadIdx.x & 31, y = threadIdx.x >> 5;
#pragma unroll
    for (int j = 0; j < 32; j += 8)
        t[y + j][x] = in[(size_t)(by + y + j) * Ccols + bx + x];
    __syncthreads();
#pragma unroll
    for (int j = 0; j < 32; j += 8)
        out[(size_t)(bx + y + j) * R + by + x] = pack_bf(t[x][y + j]);
}

// ---------------- LayerNorm -> packed bf16x2 ----------------
__global__ void __launch_bounds__(256) ln_pack_kernel(const float* __restrict__ x,
                                                      const float* __restrict__ gam,
                                                      const float* __restrict__ bet,
                                                      uint32_t* __restrict__ out) {
    int row = blockIdx.x;
    const float* xr = x + (size_t)row * DMODEL;
    int t = threadIdx.x;
    float v0 = xr[t], v1 = xr[t + 256], v2 = xr[t + 512];
    float s  = v0 + v1 + v2;
    float sq = v0 * v0 + v1 * v1 + v2 * v2;
#pragma unroll
    for (int o = 16; o; o >>= 1) {
        s  += __shfl_xor_sync(0xffffffffu, s, o);
        sq += __shfl_xor_sync(0xffffffffu, sq, o);
    }
    __shared__ float rs_[8], rq_[8];
    if ((t & 31) == 0) { rs_[t >> 5] = s; rq_[t >> 5] = sq; }
    __syncthreads();
    s = 0.f; sq = 0.f;
#pragma unroll
    for (int ww = 0; ww < 8; ww++) { s += rs_[ww]; sq += rq_[ww]; }
    float m   = s * (1.f / DMODEL);
    float var = sq * (1.f / DMODEL) - m * m;
    float inv = rsqrtf(var + 1e-5f);
    uint32_t* orow = out + (size_t)row * DMODEL;
    orow[t]       = pack_bf((v0 - m) * inv * gam[t]       + bet[t]);
    orow[t + 256] = pack_bf((v1 - m) * inv * gam[t + 256] + bet[t + 256]);
    orow[t + 512] = pack_bf((v2 - m) * inv * gam[t + 512] + bet[t + 512]);
}

// ---------------- BigBird block attention (fp32 in, packed out) ----------------
#define QS  97
#define KTS 68
#define VS  97
#define SCS 324
#define OFF_Q   0
#define OFF_KV  (64 * QS)
#define OFF_SC  (OFF_KV + 96 * KTS)
#define OFF_INV (OFF_SC + 64 * SCS)
#define ATTN_SMEM_BYTES ((OFF_INV + 64) * 4)

__global__ void __launch_bounds__(256) attn_kernel(const float* __restrict__ Q,
                                                   const float* __restrict__ K,
                                                   const float* __restrict__ V,
                                                   const int* __restrict__ kb_idx,
                                                   uint32_t* __restrict__ ctxP) {
    extern __shared__ float sm[];
    float* q_s  = sm + OFF_Q;
    float* kv   = sm + OFF_KV;
    float* sc   = sm + OFF_SC;
    float* rinv = sm + OFF_INV;

    int i  = blockIdx.x;
    int hh = blockIdx.y;
    int b  = blockIdx.z;
    int tid = threadIdx.x;
    int base = b * SEQ + i * BLKS;
    const float scale = rsqrtf((float)HDIM);

    for (int idx = tid; idx < BLKS * HDIM; idx += 256) {
        int qq = idx / HDIM, d = idx % HDIM;
        q_s[qq * QS + d] = Q[(size_t)(base + qq) * DMODEL + hh * HDIM + d] * scale;
    }

    int  kbv[NKBS];
    bool val[NKBS], dia[NKBS];
#pragma unroll
    for (int s = 0; s < NKBS; s++) {
        kbv[s] = kb_idx[i * NKBS + s];
        val[s] = (s == 0) || (kbv[s] != 0);
        dia[s] = (kbv[s] == i);
    }

    int sq0 = (tid >> 4) * 4;
    int sp0 = (tid & 15) * 4;
    __syncthreads();

    for (int s = 0; s < NKBS; s++) {
        if (val[s]) {
            __syncthreads();
            int kbase = b * SEQ + kbv[s] * BLKS;
            for (int idx = tid; idx < BLKS * HDIM; idx += 256) {
                int p = idx / HDIM, d = idx % HDIM;
                kv[d * KTS + p] = K[(size_t)(kbase + p) * DMODEL + hh * HDIM + d];
            }
            __syncthreads();
            float acc00=0,acc01=0,acc02=0,acc03=0;
            float acc10=0,acc11=0,acc12=0,acc13=0;
            float acc20=0,acc21=0,acc22=0,acc23=0;
            float acc30=0,acc31=0,acc32=0,acc33=0;
#pragma unroll 4
            for (int d = 0; d < HDIM; d++) {
                float4 bv = *(const float4*)&kv[d * KTS + sp0];
                float a0 = q_s[(sq0 + 0) * QS + d];
                float a1 = q_s[(sq0 + 1) * QS + d];
                float a2 = q_s[(sq0 + 2) * QS + d];
                float a3 = q_s[(sq0 + 3) * QS + d];
                acc00 += a0*bv.x; acc01 += a0*bv.y; acc02 += a0*bv.z; acc03 += a0*bv.w;
                acc10 += a1*bv.x; acc11 += a1*bv.y; acc12 += a1*bv.z; acc13 += a1*bv.w;
                acc20 += a2*bv.x; acc21 += a2*bv.y; acc22 += a2*bv.z; acc23 += a2*bv.w;
                acc30 += a3*bv.x; acc31 += a3*bv.y; acc32 += a3*bv.z; acc33 += a3*bv.w;
            }
            bool dg = dia[s];
            float r[4][4] = {{acc00,acc01,acc02,acc03},{acc10,acc11,acc12,acc13},
                             {acc20,acc21,acc22,acc23},{acc30,acc31,acc32,acc33}};
#pragma unroll
            for (int a = 0; a < 4; a++)
#pragma unroll
                for (int c = 0; c < 4; c++) {
                    int qq = sq0 + a, p = sp0 + c;
                    float v = r[a][c];
                    if (dg && p > qq) v = -1e9f;
                    sc[qq * SCS + s * BLKS + p] = v;
                }
        } else {
            for (int idx = tid; idx < BLKS * BLKS; idx += 256) {
                int qq = idx >> 6, p = idx & 63;
                sc[qq * SCS + s * BLKS + p] = -1e9f;
            }
        }
    }
    __syncthreads();

    {
        int qq = tid >> 2, l4 = tid & 3;
        float* row = sc + qq * SCS;
        float m = -1e30f;
        for (int idx = l4; idx < NKBS * BLKS; idx += 4) m = fmaxf(m, row[idx]);
        m = fmaxf(m, __shfl_xor_sync(0xffffffffu, m, 1));
        m = fmaxf(m, __shfl_xor_sync(0xffffffffu, m, 2));
        float ss = 0.f;
        for (int idx = l4; idx < NKBS * BLKS; idx += 4) {
            float e = __expf(row[idx] - m);
            row[idx] = e;
            ss += e;
        }
        ss += __shfl_xor_sync(0xffffffffu, ss, 1);
        ss += __shfl_xor_sync(0xffffffffu, ss, 2);
        if (l4 == 0) rinv[qq] = 1.f / ss;
    }
    __syncthreads();

    int cq0 = (tid >> 4) * 4;
    int cd0 = (tid & 15) * 6;
    float cacc[4][6];
#pragma unroll
    for (int a = 0; a < 4; a++)
#pragma unroll
        for (int k = 0; k < 6; k++) cacc[a][k] = 0.f;

    for (int s = 0; s < NKBS; s++) {
        if (!val[s]) continue;
        __syncthreads();
        int kbase = b * SEQ + kbv[s] * BLKS;
        for (int idx = tid; idx < BLKS * HDIM; idx += 256) {
            int p = idx / HDIM, d = idx % HDIM;
            kv[p * VS + d] = V[(size_t)(kbase + p) * DMODEL + hh * HDIM + d];
        }
        __syncthreads();
#pragma unroll 2
        for (int p = 0; p < BLKS; p++) {
            float pr0 = sc[(cq0 + 0) * SCS + s * BLKS + p];
            float pr1 = sc[(cq0 + 1) * SCS + s * BLKS + p];
            float pr2 = sc[(cq0 + 2) * SCS + s * BLKS + p];
            float pr3 = sc[(cq0 + 3) * SCS + s * BLKS + p];
            const float* vp = &kv[p * VS + cd0];
#pragma unroll
            for (int k = 0; k < 6; k++) {
                float vv = vp[k];
                cacc[0][k] += pr0 * vv;
                cacc[1][k] += pr1 * vv;
                cacc[2][k] += pr2 * vv;
                cacc[3][k] += pr3 * vv;
            }
        }
    }

    float r0 = rinv[cq0 + 0], r1 = rinv[cq0 + 1], r2 = rinv[cq0 + 2], r3 = rinv[cq0 + 3];
#pragma unroll
    for (int k = 0; k < 6; k++) {
        ctxP[(size_t)(base + cq0 + 0) * DMODEL + hh * HDIM + cd0 + k] = pack_bf(cacc[0][k] * r0);
        ctxP[(size_t)(base + cq0 + 1) * DMODEL + hh * HDIM + cd0 + k] = pack_bf(cacc[1][k] * r1);
        ctxP[(size_t)(base + cq0 + 2) * DMODEL + hh * HDIM + cd0 + k] = pack_bf(cacc[2][k] * r2);
        ctxP[(size_t)(base + cq0 + 3) * DMODEL + hh * HDIM + cd0 + k] = pack_bf(cacc[3][k] * r3);
    }
}

// ---------------- host launcher ----------------
extern "C" void kernel_launch(void* const* d_in, const int* in_sizes, int n_in,
                              void* d_out, int out_size) {
    const float* x    = (const float*)d_in[0];
    const float* Wq   = (const float*)d_in[1];
    const float* bq   = (const float*)d_in[2];
    const float* Wk   = (const float*)d_in[3];
    const float* bk   = (const float*)d_in[4];
    const float* Wv   = (const float*)d_in[5];
    const float* bv   = (const float*)d_in[6];
    const float* Wo   = (const float*)d_in[7];
    const float* bo   = (const float*)d_in[8];
    const float* ln_g = (const float*)d_in[9];
    const float* ln_b = (const float*)d_in[10];
    const float* W1   = (const float*)d_in[11];
    const float* b1   = (const float*)d_in[12];
    const float* W2   = (const float*)d_in[13];
    const float* b2   = (const float*)d_in[14];
    const int*   kb   = (const int*)d_in[15];
    float* out = (float*)d_out;

    uint32_t *phP, *pctxP, *pffnP, *wqT, *wkT, *wvT, *woT, *w1T, *w2T;
    float *pq, *pk, *pv, *px;
    cudaGetSymbolAddress((void**)&phP,   g_hP);
    cudaGetSymbolAddress((void**)&pctxP, g_ctxP);
    cudaGetSymbolAddress((void**)&pffnP, g_ffnP);
    cudaGetSymbolAddress((void**)&pq,    g_q);
    cudaGetSymbolAddress((void**)&pk,    g_k);
    cudaGetSymbolAddress((void**)&pv,    g_v);
    cudaGetSymbolAddress((void**)&px,    g_x);
    cudaGetSymbolAddress((void**)&wqT,   g_wqT);
    cudaGetSymbolAddress((void**)&wkT,   g_wkT);
    cudaGetSymbolAddress((void**)&wvT,   g_wvT);
    cudaGetSymbolAddress((void**)&woT,   g_woT);
    cudaGetSymbolAddress((void**)&w1T,   g_w1T);
    cudaGetSymbolAddress((void**)&w2T,   g_w2T);

    cudaFuncSetAttribute(attn_kernel, cudaFuncAttributeMaxDynamicSharedMemorySize,
                         ATTN_SMEM_BYTES);
    cudaFuncSetAttribute(gemm_bf3_kernel, cudaFuncAttributeMaxDynamicSharedMemorySize,
                         GSMEM);

    // weight transposes + pack (W[K,N] -> WT_packed[N,K])
    transpose_pack_kernel<<<dim3(DMODEL / 32, DMODEL / 32), 256>>>(Wq, wqT, DMODEL, DMODEL);
    transpose_pack_kernel<<<dim3(DMODEL / 32, DMODEL / 32), 256>>>(Wk, wkT, DMODEL, DMODEL);
    transpose_pack_kernel<<<dim3(DMODEL / 32, DMODEL / 32), 256>>>(Wv, wvT, DMODEL, DMODEL);
    transpose_pack_kernel<<<dim3(DMODEL / 32, DMODEL / 32), 256>>>(Wo, woT, DMODEL, DMODEL);
    transpose_pack_kernel<<<dim3(DFFN / 32, DMODEL / 32), 256>>>(W1, w1T, DMODEL, DFFN);
    transpose_pack_kernel<<<dim3(DMODEL / 32, DFFN / 32), 256>>>(W2, w2T, DFFN, DMODEL);

    dim3 gProj(DMODEL / 128, TOKENS / 128);   // (6,128)
    dim3 gFfn1(DFFN / 128, TOKENS / 128);     // (24,128)

    // h = LN(x) -> packed
    ln_pack_kernel<<<TOKENS, 256>>>(x, ln_g, ln_b, phP);
    // qkv (f32 out)
    gemm_bf3_kernel<<<gProj, 256, GSMEM>>>(phP, wqT, bq, nullptr, pq, nullptr, DMODEL, DMODEL, 0);
    gemm_bf3_kernel<<<gProj, 256, GSMEM>>>(phP, wkT, bk, nullptr, pk, nullptr, DMODEL, DMODEL, 0);
    gemm_bf3_kernel<<<gProj, 256, GSMEM>>>(phP, wvT, bv, nullptr, pv, nullptr, DMODEL, DMODEL, 0);
    // attention -> packed ctx
    attn_kernel<<<dim3(NBLK, NHEAD, BATCH), 256, ATTN_SMEM_BYTES>>>(pq, pk, pv, kb, pctxP);
    // x = x + ctx @ Wo + bo (f32 out)
    gemm_bf3_kernel<<<gProj, 256, GSMEM>>>(pctxP, woT, bo, x, px, nullptr, DMODEL, DMODEL, 0);
    // h2 = LN(x) -> packed
    ln_pack_kernel<<<TOKENS, 256>>>(px, ln_g, ln_b, phP);
    // ffn1: relu(h2 @ W1 + b1) -> packed
    gemm_bf3_kernel<<<gFfn1, 256, GSMEM>>>(phP, w1T, b1, nullptr, nullptr, pffnP, DMODEL, DFFN, 1);
    // ffn2: out = x + ffn @ W2 + b2 (f32 out)
    gemm_bf3_kernel<<<gProj, 256, GSMEM>>>(pffnP, w2T, b2, px, out, nullptr, DFFN, DMODEL, 0);
}